// round 1
// baseline (speedup 1.0000x reference)
#include <cuda_runtime.h>
#include <math_constants.h>

// Problem constants
#define SEQ     2048
#define NBATCH  4
#define FDIM    512
#define NQ      8192      // NBATCH * SEQ
#define NSTRIDE 1536      // q|k|v packed per token row
#define KNN     32

// Scratch (no allocations allowed): packed QKV + neighbor indices
__device__ __align__(128) float g_qkv[(size_t)NQ * NSTRIDE];   // ~50 MB
__device__ __align__(128) int   g_nn[NQ * KNN];                // 1 MB

// ---------------------------------------------------------------------------
// Fused QKV SGEMM: C[m, 0:512)=x@Wq^T, [512:1024)=x@Wk^T, [1024:1536)=x@Wv^T
// C[m,n] = sum_k A[m,k] * W[n,k]  (both operands K-major)
// 128x128x16 tiles, 256 threads, 8x8 microtile, double-buffered smem,
// register prefetch of next global tile.
// ---------------------------------------------------------------------------
__global__ void __launch_bounds__(256, 2)
gemm_qkv_kernel(const float* __restrict__ A,
                const float* __restrict__ Wq,
                const float* __restrict__ Wk,
                const float* __restrict__ Wv)
{
    __shared__ float As[2][16][128];
    __shared__ float Bs[2][16][128];

    const int n0 = blockIdx.x * 128;           // 0..1535
    const int m0 = blockIdx.y * 128;           // 0..8191
    const float* Bmat = (n0 < 512) ? Wq : (n0 < 1024) ? Wk : Wv;
    const int nloc = n0 & 511;

    const int tid = threadIdx.x;
    const int tx = tid & 15, ty = tid >> 4;

    // Global-load mapping: each thread fetches two float4s per operand tile
    const int r0 = tid >> 2;                   // 0..63
    const int c0 = (tid & 3) << 2;             // 0,4,8,12
    const int r1 = r0 + 64;

    const float* Ap = A    + (size_t)m0  * 512;
    const float* Bp = Bmat + (size_t)nloc * 512;

    float acc[8][8];
#pragma unroll
    for (int i = 0; i < 8; i++)
#pragma unroll
        for (int j = 0; j < 8; j++) acc[i][j] = 0.f;

    // Prologue: tile 0
    float4 a0 = *(const float4*)(Ap + (size_t)r0 * 512 + c0);
    float4 a1 = *(const float4*)(Ap + (size_t)r1 * 512 + c0);
    float4 b0 = *(const float4*)(Bp + (size_t)r0 * 512 + c0);
    float4 b1 = *(const float4*)(Bp + (size_t)r1 * 512 + c0);
    As[0][c0+0][r0]=a0.x; As[0][c0+1][r0]=a0.y; As[0][c0+2][r0]=a0.z; As[0][c0+3][r0]=a0.w;
    As[0][c0+0][r1]=a1.x; As[0][c0+1][r1]=a1.y; As[0][c0+2][r1]=a1.z; As[0][c0+3][r1]=a1.w;
    Bs[0][c0+0][r0]=b0.x; Bs[0][c0+1][r0]=b0.y; Bs[0][c0+2][r0]=b0.z; Bs[0][c0+3][r0]=b0.w;
    Bs[0][c0+0][r1]=b1.x; Bs[0][c0+1][r1]=b1.y; Bs[0][c0+2][r1]=b1.z; Bs[0][c0+3][r1]=b1.w;
    __syncthreads();

    int buf = 0;
#pragma unroll 1
    for (int kt = 0; kt < 32; kt++) {
        float4 na0, na1, nb0, nb1;
        const int k0 = (kt + 1) << 4;
        if (kt < 31) {
            na0 = *(const float4*)(Ap + (size_t)r0 * 512 + k0 + c0);
            na1 = *(const float4*)(Ap + (size_t)r1 * 512 + k0 + c0);
            nb0 = *(const float4*)(Bp + (size_t)r0 * 512 + k0 + c0);
            nb1 = *(const float4*)(Bp + (size_t)r1 * 512 + k0 + c0);
        }
#pragma unroll
        for (int kk = 0; kk < 16; kk++) {
            float4 x0 = *(const float4*)&As[buf][kk][ty * 8];
            float4 x1 = *(const float4*)&As[buf][kk][ty * 8 + 4];
            float4 y0 = *(const float4*)&Bs[buf][kk][tx * 8];
            float4 y1 = *(const float4*)&Bs[buf][kk][tx * 8 + 4];
            float ra[8] = {x0.x,x0.y,x0.z,x0.w,x1.x,x1.y,x1.z,x1.w};
            float rb[8] = {y0.x,y0.y,y0.z,y0.w,y1.x,y1.y,y1.z,y1.w};
#pragma unroll
            for (int i = 0; i < 8; i++)
#pragma unroll
                for (int j = 0; j < 8; j++)
                    acc[i][j] = fmaf(ra[i], rb[j], acc[i][j]);
        }
        if (kt < 31) {
            const int nb = buf ^ 1;
            As[nb][c0+0][r0]=na0.x; As[nb][c0+1][r0]=na0.y; As[nb][c0+2][r0]=na0.z; As[nb][c0+3][r0]=na0.w;
            As[nb][c0+0][r1]=na1.x; As[nb][c0+1][r1]=na1.y; As[nb][c0+2][r1]=na1.z; As[nb][c0+3][r1]=na1.w;
            Bs[nb][c0+0][r0]=nb0.x; Bs[nb][c0+1][r0]=nb0.y; Bs[nb][c0+2][r0]=nb0.z; Bs[nb][c0+3][r0]=nb0.w;
            Bs[nb][c0+0][r1]=nb1.x; Bs[nb][c0+1][r1]=nb1.y; Bs[nb][c0+2][r1]=nb1.z; Bs[nb][c0+3][r1]=nb1.w;
            __syncthreads();
            buf = nb;
        }
    }

    // Epilogue: write 8x8 per thread into packed qkv
    float* Cp = g_qkv + (size_t)(m0 + ty * 8) * NSTRIDE + n0 + tx * 8;
#pragma unroll
    for (int i = 0; i < 8; i++) {
        float4 s0 = make_float4(acc[i][0], acc[i][1], acc[i][2], acc[i][3]);
        float4 s1 = make_float4(acc[i][4], acc[i][5], acc[i][6], acc[i][7]);
        *(float4*)(Cp + (size_t)i * NSTRIDE)     = s0;
        *(float4*)(Cp + (size_t)i * NSTRIDE + 4) = s1;
    }
}

// ---------------------------------------------------------------------------
// Exact KNN (top-32 smallest squared dists, self excluded). Warp per query.
// Per-lane interleaved chunk (candidates i*32+lane), dist cache in smem
// (transposed + pad 65 -> conflict-free), cached per-lane min, extraction via
// warp argmin + cooperative rescan of the winner lane's row.
// Set semantics only (reference builds a boolean mask from the indices).
// ---------------------------------------------------------------------------
__global__ void __launch_bounds__(128)
knn_kernel(const float* __restrict__ coords)
{
    __shared__ float sd[4 * 32 * 65];   // 4 warps * (32 rows * 65)
    const unsigned FULL = 0xffffffffu;
    const int warp = threadIdx.x >> 5, lane = threadIdx.x & 31;
    const int g = blockIdx.x * 4 + warp;
    const int b = g >> 11, q = g & 2047;
    const float* cb = coords + (size_t)b * SEQ * 3;
    const float qx = cb[q * 3 + 0], qy = cb[q * 3 + 1], qz = cb[q * 3 + 2];
    float* sw = sd + warp * 2080;
    const float FINF = CUDART_INF_F;

    float best = FINF; int bestc = 0;
    float* srow = sw + lane * 65;
#pragma unroll 4
    for (int i = 0; i < 64; i++) {
        const int c = i * 32 + lane;
        const float dx = cb[c * 3 + 0] - qx;
        const float dy = cb[c * 3 + 1] - qy;
        const float dz = cb[c * 3 + 2] - qz;
        float d = dx * dx + dy * dy + dz * dz;
        if (c == q) d = FINF;                 // exclude self (argsort drops it)
        srow[i] = d;
        if (d < best) { best = d; bestc = c; }
    }
    __syncwarp();

    int myNN = 0;
    for (int r = 0; r < KNN; r++) {
        // global argmin over per-lane cached minima (tie-break by index ->
        // every lane converges to the identical winner)
        float v = best; int c = bestc;
#pragma unroll
        for (int off = 16; off; off >>= 1) {
            float v2 = __shfl_xor_sync(FULL, v, off);
            int   c2 = __shfl_xor_sync(FULL, c, off);
            if (v2 < v || (v2 == v && c2 < c)) { v = v2; c = c2; }
        }
        if (lane == r) myNN = c;

        const int L = c & 31, iW = c >> 5;
        float* rrow = sw + L * 65;
        if (lane == (iW & 31)) rrow[iW] = FINF;   // permanently remove winner
        __syncwarp();

        // cooperative rescan of lane L's 64 candidates
        float a0 = rrow[lane];
        float a1 = rrow[lane + 32];
        float nv; int ni;
        if (a0 <= a1) { nv = a0; ni = lane; } else { nv = a1; ni = lane + 32; }
#pragma unroll
        for (int off = 16; off; off >>= 1) {
            float v2 = __shfl_xor_sync(FULL, nv, off);
            int   i2 = __shfl_xor_sync(FULL, ni, off);
            if (v2 < nv || (v2 == nv && i2 < ni)) { nv = v2; ni = i2; }
        }
        if (lane == L) { best = nv; bestc = ni * 32 + L; }
    }
    g_nn[g * KNN + lane] = myNN;
}

// ---------------------------------------------------------------------------
// Sparse attention: block per query (256 thr = 8 warps = 8 heads).
// Lane j: score for neighbor j (64-long dot, float4). Warp softmax over 32.
// Output: lane d accumulates d and d+32 with coalesced V gathers (L2-hot).
// ---------------------------------------------------------------------------
__global__ void __launch_bounds__(256)
attn_kernel(float* __restrict__ out)
{
    __shared__ __align__(16) float qs[512];
    __shared__ int nns[KNN];
    const unsigned FULL = 0xffffffffu;
    const int g = blockIdx.x;
    const int b = g >> 11;
    const int tid = threadIdx.x;
    const int h = tid >> 5, lane = tid & 31;

    const float* qrow = g_qkv + (size_t)g * NSTRIDE;
    qs[tid]       = qrow[tid];
    qs[tid + 256] = qrow[tid + 256];
    if (tid < KNN) nns[tid] = g_nn[g * KNN + tid];
    __syncthreads();

    const int base_tok = b << 11;

    // scores
    const int cme = nns[lane];
    const float4* k4 = (const float4*)(g_qkv + (size_t)(base_tok + cme) * NSTRIDE + 512 + h * 64);
    const float4* q4 = (const float4*)(qs + h * 64);
    float s = 0.f;
#pragma unroll
    for (int i = 0; i < 16; i++) {
        float4 kv = k4[i], qv = q4[i];
        s += kv.x * qv.x; s += kv.y * qv.y; s += kv.z * qv.z; s += kv.w * qv.w;
    }
    s *= 0.125f;   // 1/sqrt(64)

    // softmax across the 32 neighbors (one per lane)
    float m = s;
#pragma unroll
    for (int off = 16; off; off >>= 1) m = fmaxf(m, __shfl_xor_sync(FULL, m, off));
    const float e = expf(s - m);
    float sum = e;
#pragma unroll
    for (int off = 16; off; off >>= 1) sum += __shfl_xor_sync(FULL, sum, off);
    const float w = e / sum;

    // weighted V accumulation, coalesced per-j
    float acc0 = 0.f, acc1 = 0.f;
#pragma unroll 4
    for (int j = 0; j < KNN; j++) {
        const float wj = __shfl_sync(FULL, w, j);
        const int cj = nns[j];
        const float* vrow = g_qkv + (size_t)(base_tok + cj) * NSTRIDE + 1024 + h * 64;
        acc0 = fmaf(wj, vrow[lane],      acc0);
        acc1 = fmaf(wj, vrow[lane + 32], acc1);
    }
    float* orow = out + (size_t)g * 512 + h * 64;
    orow[lane]      = acc0;
    orow[lane + 32] = acc1;
}

// ---------------------------------------------------------------------------
// metric[b,h,d] = mean_s K[b,s,h*64+d]. Kahan-compensated fp32 sum
// (mean magnitude ~0.02; naive sequential sum error would be ~1e-4 abs).
// ---------------------------------------------------------------------------
__global__ void __launch_bounds__(512)
metric_kernel(float* __restrict__ out)
{
    const int b = blockIdx.x, f = threadIdx.x;
    const float* base = g_qkv + (size_t)b * SEQ * NSTRIDE + 512 + f;
    float s = 0.f, comp = 0.f;
    for (int i = 0; i < SEQ; i++) {
        float y = base[(size_t)i * NSTRIDE] - comp;
        float t = s + y;
        comp = (t - s) - y;
        s = t;
    }
    out[(size_t)NQ * FDIM + (size_t)b * 512 + f] = s * (1.0f / 2048.0f);
}

// ---------------------------------------------------------------------------
extern "C" void kernel_launch(void* const* d_in, const int* in_sizes, int n_in,
                              void* d_out, int out_size)
{
    const float* x      = (const float*)d_in[0];
    const float* coords = (const float*)d_in[1];
    const float* Wq     = (const float*)d_in[2];
    const float* Wk     = (const float*)d_in[3];
    const float* Wv     = (const float*)d_in[4];
    float* out = (float*)d_out;

    dim3 ggrid(12, 64);                       // N-tiles x M-tiles
    gemm_qkv_kernel<<<ggrid, 256>>>(x, Wq, Wk, Wv);
    knn_kernel<<<2048, 128>>>(coords);        // independent of GEMM
    attn_kernel<<<8192, 256>>>(out);          // needs g_qkv + g_nn
    metric_kernel<<<4, 512>>>(out);           // needs g_qkv (K part)
}

// round 8
// speedup vs baseline: 1.5079x; 1.5079x over previous
#include <cuda_runtime.h>
#include <cuda_bf16.h>
#include <math_constants.h>
#include <cstdint>

// Problem constants
#define SEQ     2048
#define NBATCH  4
#define FDIM    512
#define NQ      8192      // NBATCH * SEQ
#define NSTRIDE 1536      // q|k|v packed per token row
#define KNN     32

// GEMM tiling (single 32KB static-shared buffer -> no cudaFuncSetAttribute)
#define BM 128
#define BN 128
#define SKC 32            // K elems per staged chunk
#define NCH 16            // 512 / 32

// smem byte offsets inside the single buffer; rows are 64B (32 bf16), SW64
#define OFF_AHI 0
#define OFF_ALO (8*1024)
#define OFF_BHI (16*1024)
#define OFF_BLO (24*1024)

// Scratch (no allocations allowed): packed QKV + neighbor indices
__device__ __align__(128) float g_qkv[(size_t)NQ * NSTRIDE];   // ~50 MB
__device__ __align__(128) int   g_nn[NQ * KNN];                // 1 MB

// ---------------------------------------------------------------------------
__device__ __forceinline__ uint32_t smem_u32(const void* p) {
    uint32_t a;
    asm("{ .reg .u64 t; cvta.to.shared.u64 t, %1; cvt.u32.u64 %0, t; }" : "=r"(a) : "l"(p));
    return a;
}
#define SW64(off) ((off) ^ (((off) >> 3) & 0x30))

// Split fp32 into hi/lo bf16 (x == hi + lo + O(2^-18 x))
__device__ __forceinline__ void split_bf16(float x, uint32_t& h, uint32_t& l) {
    __nv_bfloat16 bh = __float2bfloat16_rn(x);
    float r = x - __bfloat162float(bh);           // exact in fp32
    __nv_bfloat16 bl = __float2bfloat16_rn(r);
    h = (uint32_t)__bfloat16_as_ushort(bh);
    l = (uint32_t)__bfloat16_as_ushort(bl);
}

// Pack 8 fp32 -> 16B hi-bf16 + 16B lo-bf16
__device__ __forceinline__ void pack8(const float4& f0, const float4& f1,
                                      uint4& hi, uint4& lo) {
    uint32_t h0,l0,h1,l1,h2,l2,h3,l3,h4,l4,h5,l5,h6,l6,h7,l7;
    split_bf16(f0.x,h0,l0); split_bf16(f0.y,h1,l1);
    split_bf16(f0.z,h2,l2); split_bf16(f0.w,h3,l3);
    split_bf16(f1.x,h4,l4); split_bf16(f1.y,h5,l5);
    split_bf16(f1.z,h6,l6); split_bf16(f1.w,h7,l7);
    hi.x = h0 | (h1<<16); hi.y = h2 | (h3<<16); hi.z = h4 | (h5<<16); hi.w = h6 | (h7<<16);
    lo.x = l0 | (l1<<16); lo.y = l2 | (l3<<16); lo.z = l4 | (l5<<16); lo.w = l6 | (l7<<16);
}

__device__ __forceinline__ void ldsm_x4(uint32_t a, uint32_t& r0, uint32_t& r1,
                                        uint32_t& r2, uint32_t& r3) {
    asm volatile("ldmatrix.sync.aligned.m8n8.x4.shared.b16 {%0,%1,%2,%3}, [%4];"
                 : "=r"(r0), "=r"(r1), "=r"(r2), "=r"(r3) : "r"(a));
}
__device__ __forceinline__ void ldsm_x2(uint32_t a, uint32_t& r0, uint32_t& r1) {
    asm volatile("ldmatrix.sync.aligned.m8n8.x2.shared.b16 {%0,%1}, [%2];"
                 : "=r"(r0), "=r"(r1) : "r"(a));
}
__device__ __forceinline__ void mma_bf16(float* d, const uint32_t* a, const uint32_t* b) {
    asm volatile("mma.sync.aligned.m16n8k16.row.col.f32.bf16.bf16.f32 "
                 "{%0,%1,%2,%3}, {%4,%5,%6,%7}, {%8,%9}, {%0,%1,%2,%3};"
                 : "+f"(d[0]), "+f"(d[1]), "+f"(d[2]), "+f"(d[3])
                 : "r"(a[0]), "r"(a[1]), "r"(a[2]), "r"(a[3]), "r"(b[0]), "r"(b[1]));
}

// ---------------------------------------------------------------------------
// QKV GEMM: C[m,n] = sum_k x[m,k] * W[n,k], fp32 via bf16 3-term split on
// mma.sync (base-target ISA; tcgen05 not available at compute_103).
// CTA 128x128, 8 warps in 2(M)x4(N), warp tile 64x32. KC=32, single 32KB
// static-shared buffer, global prefetch into registers hides LDG latency.
// ---------------------------------------------------------------------------
__global__ void __launch_bounds__(256, 1)
gemm_mma_kernel(const float* __restrict__ A,
                const float* __restrict__ Wq,
                const float* __restrict__ Wk,
                const float* __restrict__ Wv)
{
    __shared__ __align__(1024) char smem[32 * 1024];
    const uint32_t sbase = smem_u32(smem);

    const int tid  = threadIdx.x;
    const int wid  = tid >> 5;
    const int lane = tid & 31;
    const int wm   = wid >> 2;         // 0..1  (M position)
    const int wn   = wid & 3;          // 0..3  (N position)

    const int n0 = blockIdx.x * BN;    // 0..1535
    const int m0 = blockIdx.y * BM;    // 0..8191
    const float* Bmat = (n0 < 512) ? Wq : (n0 < 1024) ? Wk : Wv;
    const int nloc = n0 & 511;

    // loader mapping: thread t -> row t>>1 (0..127), col half (t&1)*16 elems
    const int lrow  = tid >> 1;
    const int lcol  = (tid & 1) * 16;             // fp32 elems within chunk
    const float* Ap = A    + (size_t)(m0   + lrow) * 512 + lcol;
    const float* Bp = Bmat + (size_t)(nloc + lrow) * 512 + lcol;

    // staging offsets: 2 groups of 8 elems (16B each), SW64 on 64B rows
    uint32_t st_off[2];
#pragma unroll
    for (int g = 0; g < 2; g++)
        st_off[g] = SW64((uint32_t)(lrow * 64 + lcol * 2 + g * 16));

    // ldmatrix per-lane byte offsets (within operand region, before SW64)
    uint32_t a_off[4];
    {
        const int r  = wm * 64 + (lane & 15);
        const int kh = (lane >> 4) * 16;          // k-half (8 elems = 16B)
#pragma unroll
        for (int mt = 0; mt < 4; mt++)
            a_off[mt] = (uint32_t)((r + mt * 16) * 64 + kh);
    }
    uint32_t b_off[4];
    {
        const int r  = wn * 32 + (lane & 7);
        const int kh = ((lane >> 3) & 1) * 16;    // lanes 16-31 unused by x2
#pragma unroll
        for (int nt = 0; nt < 4; nt++)
            b_off[nt] = (uint32_t)((r + nt * 8) * 64 + kh);
    }

    float acc[4][4][4];
#pragma unroll
    for (int i = 0; i < 4; i++)
#pragma unroll
        for (int j = 0; j < 4; j++)
#pragma unroll
            for (int r = 0; r < 4; r++) acc[i][j][r] = 0.f;

    float4 ra0, ra1, ra2, ra3, rb0, rb1, rb2, rb3;   // staged next-chunk globals

    // prologue: load + stage chunk 0
    ra0 = *(const float4*)(Ap + 0);  ra1 = *(const float4*)(Ap + 4);
    ra2 = *(const float4*)(Ap + 8);  ra3 = *(const float4*)(Ap + 12);
    rb0 = *(const float4*)(Bp + 0);  rb1 = *(const float4*)(Bp + 4);
    rb2 = *(const float4*)(Bp + 8);  rb3 = *(const float4*)(Bp + 12);
    {
        uint4 hi, lo;
        pack8(ra0, ra1, hi, lo);
        *(uint4*)(smem + OFF_AHI + st_off[0]) = hi;
        *(uint4*)(smem + OFF_ALO + st_off[0]) = lo;
        pack8(ra2, ra3, hi, lo);
        *(uint4*)(smem + OFF_AHI + st_off[1]) = hi;
        *(uint4*)(smem + OFF_ALO + st_off[1]) = lo;
        pack8(rb0, rb1, hi, lo);
        *(uint4*)(smem + OFF_BHI + st_off[0]) = hi;
        *(uint4*)(smem + OFF_BLO + st_off[0]) = lo;
        pack8(rb2, rb3, hi, lo);
        *(uint4*)(smem + OFF_BHI + st_off[1]) = hi;
        *(uint4*)(smem + OFF_BLO + st_off[1]) = lo;
    }
    __syncthreads();

#pragma unroll 1
    for (int c = 0; c < NCH; c++) {
        // prefetch next chunk's globals into registers (hidden under MMA)
        if (c < NCH - 1) {
            const int kc = (c + 1) * SKC;
            ra0 = *(const float4*)(Ap + kc + 0);  ra1 = *(const float4*)(Ap + kc + 4);
            ra2 = *(const float4*)(Ap + kc + 8);  ra3 = *(const float4*)(Ap + kc + 12);
            rb0 = *(const float4*)(Bp + kc + 0);  rb1 = *(const float4*)(Bp + kc + 4);
            rb2 = *(const float4*)(Bp + kc + 8);  rb3 = *(const float4*)(Bp + kc + 12);
        }

        // MMA over the buffer: 2 K16-steps
#pragma unroll
        for (int ks = 0; ks < 2; ks++) {
            const uint32_t kso = (uint32_t)(ks * 32);    // 16 elems = 32B
            uint32_t ah[4][4], al[4][4], bh[4][2], bl[4][2];
#pragma unroll
            for (int mt = 0; mt < 4; mt++) {
                const uint32_t o = SW64(a_off[mt] + kso);
                ldsm_x4(sbase + OFF_AHI + o, ah[mt][0], ah[mt][1], ah[mt][2], ah[mt][3]);
                ldsm_x4(sbase + OFF_ALO + o, al[mt][0], al[mt][1], al[mt][2], al[mt][3]);
            }
#pragma unroll
            for (int nt = 0; nt < 4; nt++) {
                const uint32_t o = SW64(b_off[nt] + kso);
                ldsm_x2(sbase + OFF_BHI + o, bh[nt][0], bh[nt][1]);
                ldsm_x2(sbase + OFF_BLO + o, bl[nt][0], bl[nt][1]);
            }
#pragma unroll
            for (int mt = 0; mt < 4; mt++)
#pragma unroll
                for (int nt = 0; nt < 4; nt++) {
                    mma_bf16(acc[mt][nt], ah[mt], bh[nt]);   // hi*hi
                    mma_bf16(acc[mt][nt], ah[mt], bl[nt]);   // hi*lo
                    mma_bf16(acc[mt][nt], al[mt], bh[nt]);   // lo*hi
                }
        }

        // restage buffer with the prefetched chunk
        if (c < NCH - 1) {
            __syncthreads();     // everyone done reading the buffer
            uint4 hi, lo;
            pack8(ra0, ra1, hi, lo);
            *(uint4*)(smem + OFF_AHI + st_off[0]) = hi;
            *(uint4*)(smem + OFF_ALO + st_off[0]) = lo;
            pack8(ra2, ra3, hi, lo);
            *(uint4*)(smem + OFF_AHI + st_off[1]) = hi;
            *(uint4*)(smem + OFF_ALO + st_off[1]) = lo;
            pack8(rb0, rb1, hi, lo);
            *(uint4*)(smem + OFF_BHI + st_off[0]) = hi;
            *(uint4*)(smem + OFF_BLO + st_off[0]) = lo;
            pack8(rb2, rb3, hi, lo);
            *(uint4*)(smem + OFF_BHI + st_off[1]) = hi;
            *(uint4*)(smem + OFF_BLO + st_off[1]) = lo;
            __syncthreads();     // new data visible
        }
    }

    // epilogue: acc -> g_qkv. c0,c1 -> (row qr, cols 2qc,2qc+1); c2,c3 -> row qr+8
    {
        const int qr = lane >> 2, qc = lane & 3;
#pragma unroll
        for (int mt = 0; mt < 4; mt++) {
            const int row = m0 + wm * 64 + mt * 16 + qr;
            float* o0 = g_qkv + (size_t)row * NSTRIDE + n0 + wn * 32;
            float* o1 = g_qkv + (size_t)(row + 8) * NSTRIDE + n0 + wn * 32;
#pragma unroll
            for (int nt = 0; nt < 4; nt++) {
                const int col = nt * 8 + 2 * qc;
                *(float2*)(o0 + col) = make_float2(acc[mt][nt][0], acc[mt][nt][1]);
                *(float2*)(o1 + col) = make_float2(acc[mt][nt][2], acc[mt][nt][3]);
            }
        }
    }
}

// ---------------------------------------------------------------------------
// Exact KNN (top-32 smallest squared dists, self excluded). Warp per query.
// ---------------------------------------------------------------------------
__global__ void __launch_bounds__(128)
knn_kernel(const float* __restrict__ coords)
{
    __shared__ float sd[4 * 32 * 65];
    const unsigned FULL = 0xffffffffu;
    const int warp = threadIdx.x >> 5, lane = threadIdx.x & 31;
    const int g = blockIdx.x * 4 + warp;
    const int b = g >> 11, q = g & 2047;
    const float* cb = coords + (size_t)b * SEQ * 3;
    const float qx = cb[q * 3 + 0], qy = cb[q * 3 + 1], qz = cb[q * 3 + 2];
    float* sw = sd + warp * 2080;
    const float FINF = CUDART_INF_F;

    float best = FINF; int bestc = 0;
    float* srow = sw + lane * 65;
#pragma unroll 4
    for (int i = 0; i < 64; i++) {
        const int c = i * 32 + lane;
        const float dx = cb[c * 3 + 0] - qx;
        const float dy = cb[c * 3 + 1] - qy;
        const float dz = cb[c * 3 + 2] - qz;
        float d = dx * dx + dy * dy + dz * dz;
        if (c == q) d = FINF;
        srow[i] = d;
        if (d < best) { best = d; bestc = c; }
    }
    __syncwarp();

    int myNN = 0;
    for (int r = 0; r < KNN; r++) {
        float v = best; int c = bestc;
#pragma unroll
        for (int off = 16; off; off >>= 1) {
            float v2 = __shfl_xor_sync(FULL, v, off);
            int   c2 = __shfl_xor_sync(FULL, c, off);
            if (v2 < v || (v2 == v && c2 < c)) { v = v2; c = c2; }
        }
        if (lane == r) myNN = c;

        const int L = c & 31, iW = c >> 5;
        float* rrow = sw + L * 65;
        if (lane == (iW & 31)) rrow[iW] = FINF;
        __syncwarp();

        float a0 = rrow[lane];
        float a1 = rrow[lane + 32];
        float nv; int ni;
        if (a0 <= a1) { nv = a0; ni = lane; } else { nv = a1; ni = lane + 32; }
#pragma unroll
        for (int off = 16; off; off >>= 1) {
            float v2 = __shfl_xor_sync(FULL, nv, off);
            int   i2 = __shfl_xor_sync(FULL, ni, off);
            if (v2 < nv || (v2 == nv && i2 < ni)) { nv = v2; ni = i2; }
        }
        if (lane == L) { best = nv; bestc = ni * 32 + L; }
    }
    g_nn[g * KNN + lane] = myNN;
}

// ---------------------------------------------------------------------------
// Sparse attention: block per query (256 thr = 8 warps = 8 heads).
// ---------------------------------------------------------------------------
__global__ void __launch_bounds__(256)
attn_kernel(float* __restrict__ out)
{
    __shared__ __align__(16) float qs[512];
    __shared__ int nns[KNN];
    const unsigned FULL = 0xffffffffu;
    const int g = blockIdx.x;
    const int b = g >> 11;
    const int tid = threadIdx.x;
    const int h = tid >> 5, lane = tid & 31;

    const float* qrow = g_qkv + (size_t)g * NSTRIDE;
    qs[tid]       = qrow[tid];
    qs[tid + 256] = qrow[tid + 256];
    if (tid < KNN) nns[tid] = g_nn[g * KNN + tid];
    __syncthreads();

    const int base_tok = b << 11;

    const int cme = nns[lane];
    const float4* k4 = (const float4*)(g_qkv + (size_t)(base_tok + cme) * NSTRIDE + 512 + h * 64);
    const float4* q4 = (const float4*)(qs + h * 64);
    float s = 0.f;
#pragma unroll
    for (int i = 0; i < 16; i++) {
        float4 kv = k4[i], qv = q4[i];
        s += kv.x * qv.x; s += kv.y * qv.y; s += kv.z * qv.z; s += kv.w * qv.w;
    }
    s *= 0.125f;

    float m = s;
#pragma unroll
    for (int off = 16; off; off >>= 1) m = fmaxf(m, __shfl_xor_sync(FULL, m, off));
    const float e = expf(s - m);
    float sum = e;
#pragma unroll
    for (int off = 16; off; off >>= 1) sum += __shfl_xor_sync(FULL, sum, off);
    const float w = e / sum;

    float acc0 = 0.f, acc1 = 0.f;
#pragma unroll 4
    for (int j = 0; j < KNN; j++) {
        const float wj = __shfl_sync(FULL, w, j);
        const int cj = nns[j];
        const float* vrow = g_qkv + (size_t)(base_tok + cj) * NSTRIDE + 1024 + h * 64;
        acc0 = fmaf(wj, vrow[lane],      acc0);
        acc1 = fmaf(wj, vrow[lane + 32], acc1);
    }
    float* orow = out + (size_t)g * 512 + h * 64;
    orow[lane]      = acc0;
    orow[lane + 32] = acc1;
}

// ---------------------------------------------------------------------------
// metric[b,h,d] = mean_s K[b,s,h*64+d]. 64 blocks x 512 threads:
// Kahan within a 128-row slice + deterministic smem tree.
// ---------------------------------------------------------------------------
__global__ void __launch_bounds__(512)
metric_kernel(float* __restrict__ out)
{
    __shared__ float sp[512];
    const int b = blockIdx.x, fb = blockIdx.y * 32;
    const int fi = threadIdx.x & 31, sl = threadIdx.x >> 5;
    const float* base = g_qkv + (size_t)b * SEQ * NSTRIDE + 512 + fb + fi
                      + (size_t)sl * 128 * NSTRIDE;
    float s = 0.f, comp = 0.f;
#pragma unroll 4
    for (int i = 0; i < 128; i++) {
        float y = base[(size_t)i * NSTRIDE] - comp;
        float t = s + y;
        comp = (t - s) - y;
        s = t;
    }
    sp[sl * 32 + fi] = s;
    __syncthreads();
#pragma unroll
    for (int st = 8; st >= 1; st >>= 1) {
        if (sl < st) sp[sl * 32 + fi] += sp[(sl + st) * 32 + fi];
        __syncthreads();
    }
    if (sl == 0)
        out[(size_t)NQ * FDIM + (size_t)b * 512 + fb + fi] = sp[fi] * (1.0f / 2048.0f);
}

// ---------------------------------------------------------------------------
extern "C" void kernel_launch(void* const* d_in, const int* in_sizes, int n_in,
                              void* d_out, int out_size)
{
    const float* x      = (const float*)d_in[0];
    const float* coords = (const float*)d_in[1];
    const float* Wq     = (const float*)d_in[2];
    const float* Wk     = (const float*)d_in[3];
    const float* Wv     = (const float*)d_in[4];
    float* out = (float*)d_out;

    knn_kernel<<<2048, 128>>>(coords);                    // coords only
    gemm_mma_kernel<<<dim3(12, 64), 256>>>(x, Wq, Wk, Wv);
    attn_kernel<<<8192, 256>>>(out);                      // needs g_qkv + g_nn
    metric_kernel<<<dim3(4, 16), 512>>>(out);             // needs g_qkv (K part)
}